// round 10
// baseline (speedup 1.0000x reference)
#include <cuda_runtime.h>
#include <cuda.h>
#include <cuda_fp16.h>
#include <math.h>
#include <stdint.h>

#define BB 8
#define TT 2048
#define NF 1024
#define BT (BB*TT)            // 16384
#define KK NF                 // GEMM K = 1024
#define NCH 16                // scan chunks
#define CHT (TT/NCH)          // 128
#define NCHAN (BB*NF)         // 8192

// GEMM tiling: 128x128x64 block, 128 threads, 4 warps (2x2) of 64x64, TMA loads
#define BM 128
#define BN 128
#define BK 64                 // halves; 128 bytes -> SW128 row
#define STAGES 3
#define NKIT (KK/BK)          // 16
#define TILEB (BM*BK*2)       // 16384 bytes per A (or B) tile
#define SM_FULL 0             // 3 x 8B
#define SM_FREE 24            // 3 x 8B
#define SM_TILES 1024
#define SMEM_BYTES (SM_TILES + STAGES*2*TILEB)   // 99328

// ---------------- scratch (device globals; no allocs allowed) ----------------
__device__ float g_wi [(size_t)BT*NF];
__device__ float g_wig[(size_t)BT*NF];
__device__ float g_r  [(size_t)BT*NF];
__device__ float g_og [(size_t)BT*NF];
__device__ __half g_xh [(size_t)BT*NF];
__device__ __half g_zh [(size_t)BT*NF];
__device__ __half g_w4 [(size_t)4*NF*NF];      // proj weights fp16: r, i, ig, og
__device__ __half g_woh[(size_t)NF*NF];
__device__ float g_sa [NCH*NCHAN];
__device__ float g_sb [NCH*NCHAN];
__device__ float g_hs [NCH*NCHAN];

__device__ __forceinline__ float sigf(float v) {
    return 1.0f / (1.0f + __expf(-v));
}
__device__ __forceinline__ uint32_t smem_u32(const void* p) {
    return (uint32_t)__cvta_generic_to_shared(p);
}

#define MMA_F16(d, a, b)                                               \
    asm volatile(                                                      \
        "mma.sync.aligned.m16n8k16.row.col.f32.f16.f16.f32 "           \
        "{%0,%1,%2,%3},{%4,%5,%6,%7},{%8,%9},{%0,%1,%2,%3};\n"         \
        : "+f"(d[0]), "+f"(d[1]), "+f"(d[2]), "+f"(d[3])               \
        : "r"(a[0]), "r"(a[1]), "r"(a[2]), "r"(a[3]),                  \
          "r"(b[0]), "r"(b[1]))

#define LDMX4(r0, r1, r2, r3, addr)                                            \
    asm volatile("ldmatrix.sync.aligned.m8n8.x4.shared.b16 {%0,%1,%2,%3},[%4];\n" \
                 : "=r"(r0), "=r"(r1), "=r"(r2), "=r"(r3) : "r"(addr))

#define MBAR_INIT(addr, cnt) \
    asm volatile("mbarrier.init.shared.b64 [%0], %1;" :: "r"(addr), "r"(cnt) : "memory")
#define MBAR_EXPECT_TX(addr, bytes) \
    asm volatile("mbarrier.arrive.expect_tx.shared.b64 _, [%0], %1;" :: "r"(addr), "r"(bytes) : "memory")
#define MBAR_ARRIVE(addr) \
    asm volatile("mbarrier.arrive.shared.b64 _, [%0];" :: "r"(addr) : "memory")

__device__ __forceinline__ void mbar_wait(uint32_t addr, uint32_t parity) {
    uint32_t done;
    asm volatile(
        "{\n\t.reg .pred p;\n\t"
        "mbarrier.try_wait.parity.acquire.cta.shared::cta.b64 p, [%1], %2;\n\t"
        "selp.b32 %0, 1, 0, p;\n\t}"
        : "=r"(done) : "r"(addr), "r"(parity) : "memory");
    if (!done) {
        asm volatile(
            "{\n\t.reg .pred P1;\n\t"
            "WL_%=:\n\t"
            "mbarrier.try_wait.parity.acquire.cta.shared::cta.b64 P1, [%0], %1, 0x989680;\n\t"
            "@P1 bra.uni WD_%=;\n\t"
            "bra.uni WL_%=;\n\t"
            "WD_%=:\n\t}"
            :: "r"(addr), "r"(parity) : "memory");
    }
}

__device__ __forceinline__ void tma2d(uint32_t smem_addr, const CUtensorMap* tmap,
                                      int cx, int cy, uint32_t mbar) {
    asm volatile(
        "cp.async.bulk.tensor.2d.shared::cta.global.tile.mbarrier::complete_tx::bytes "
        "[%0], [%1, {%2, %3}], [%4];"
        :: "r"(smem_addr), "l"(tmap), "r"(cx), "r"(cy), "r"(mbar) : "memory");
}

// SW128 swizzle for a [rows x 128B] tile
__device__ __forceinline__ uint32_t sw128(uint32_t off) {
    return off ^ ((off >> 3) & 0x70);
}

struct EpiArgs {
    float* out[4];
    const float* bias[4];
};

// ---------------------------------------------------------------------------
// fp16 HMMA GEMM with TMA loads: C[i,j] = sum_k A[i,k]*B[j,k]
// 128x128x64 block, 128 thr, 4 warps (2m x 2n) of 64x64.
// 3-stage TMA + mbarrier ring; ldmatrix on SW128 tiles; register-DB fragments.
// ---------------------------------------------------------------------------
__global__ void __launch_bounds__(128, 2)
hgemm_tma(const __grid_constant__ CUtensorMap tmA,
          const __grid_constant__ CUtensorMap tmB,
          EpiArgs ea)
{
    extern __shared__ __align__(1024) char smem[];
    const uint32_t sb = smem_u32(smem);
    const int tid  = threadIdx.x;
    const int warp = tid >> 5, lane = tid & 31;
    const int wm = warp >> 1, wn = warp & 1;
    const int bm = blockIdx.y * BM;
    const int bn = blockIdx.x * BN;

    if (tid == 0) {
#pragma unroll
        for (int s = 0; s < STAGES; s++) {
            MBAR_INIT(sb + SM_FULL + 8*s, 1);
            MBAR_INIT(sb + SM_FREE + 8*s, 128);
        }
        asm volatile("fence.proxy.async.shared::cta;" ::: "memory");
    }
    __syncthreads();

    if (tid == 0) {
        const CUtensorMap* pA = &tmA;
        const CUtensorMap* pB = &tmB;
        asm volatile("prefetch.tensormap [%0];" :: "l"(pA));
        asm volatile("prefetch.tensormap [%0];" :: "l"(pB));
#pragma unroll
        for (int p = 0; p < STAGES; p++) {
            MBAR_EXPECT_TX(sb + SM_FULL + 8*p, 2u * TILEB);
            tma2d(sb + SM_TILES + p*2*TILEB,         pA, p*BK, bm, sb + SM_FULL + 8*p);
            tma2d(sb + SM_TILES + p*2*TILEB + TILEB, pB, p*BK, bn, sb + SM_FULL + 8*p);
        }
    }

    float acc[4][8][4];
#pragma unroll
    for (int i = 0; i < 4; i++)
#pragma unroll
        for (int j = 0; j < 8; j++)
#pragma unroll
            for (int q = 0; q < 4; q++) acc[i][j][q] = 0.0f;

    uint32_t af[2][4][4], bf[2][8][2];

    // swizzled in-tile byte offsets (row*128 + ks*32 + (lane>>4)*16)
    const uint32_t a_row = wm * 64 + (lane & 15);
    const uint32_t b_row = wn * 64 + (lane & 15);
    const uint32_t coff  = (lane >> 4) * 16;

#define LDFRAG(buf, sbase, ks)                                                     \
    do {                                                                           \
        _Pragma("unroll")                                                          \
        for (int i = 0; i < 4; i++) {                                              \
            uint32_t off = (a_row + i * 16) * 128 + (ks) * 32 + coff;              \
            LDMX4(af[buf][i][0], af[buf][i][1], af[buf][i][2], af[buf][i][3],      \
                  (sbase) + sw128(off));                                           \
        }                                                                          \
        _Pragma("unroll")                                                          \
        for (int g = 0; g < 4; g++) {                                              \
            uint32_t t0, t1, t2, t3;                                               \
            uint32_t off = (b_row + g * 16) * 128 + (ks) * 32 + coff;              \
            LDMX4(t0, t1, t2, t3, (sbase) + TILEB + sw128(off));                   \
            bf[buf][2*g][0]   = t0; bf[buf][2*g][1]   = t2;                        \
            bf[buf][2*g+1][0] = t1; bf[buf][2*g+1][1] = t3;                        \
        }                                                                          \
    } while (0)

#define DO_MMA(buf)                                                \
    do {                                                           \
        _Pragma("unroll")                                          \
        for (int i = 0; i < 4; i++)                                \
            _Pragma("unroll")                                      \
            for (int j = 0; j < 8; j++)                            \
                MMA_F16(acc[i][j], af[buf][i], bf[buf][j]);        \
    } while (0)

    int fullph[STAGES] = {0, 0, 0};
    int freeph[STAGES] = {0, 0, 0};

#pragma unroll 1
    for (int kt = 0; kt < NKIT; kt++) {
        const int s = kt % STAGES;
        const uint32_t sbase = sb + SM_TILES + s * 2 * TILEB;

        mbar_wait(sb + SM_FULL + 8*s, fullph[s]);
        fullph[s] ^= 1;

        LDFRAG(0, sbase, 0);
#pragma unroll
        for (int ks = 0; ks < 4; ks++) {
            if (ks < 3) LDFRAG((ks + 1) & 1, sbase, ks + 1);
            DO_MMA(ks & 1);
        }

        MBAR_ARRIVE(sb + SM_FREE + 8*s);
        if (tid == 0 && kt + STAGES < NKIT) {
            mbar_wait(sb + SM_FREE + 8*s, freeph[s]);
            freeph[s] ^= 1;
            MBAR_EXPECT_TX(sb + SM_FULL + 8*s, 2u * TILEB);
            tma2d(sbase,         &tmA, (kt + STAGES) * BK, bm, sb + SM_FULL + 8*s);
            tma2d(sbase + TILEB, &tmB, (kt + STAGES) * BK, bn, sb + SM_FULL + 8*s);
        }
    }

    // ---- epilogue ----
    const int seg = bn >> 10;
    float* outp = ea.out[seg];
    const float* biasp = ea.bias[seg];
    const int lr = lane >> 2;
    const int lc = (lane & 3) * 2;

#pragma unroll
    for (int i = 0; i < 4; i++) {
#pragma unroll
        for (int j = 0; j < 8; j++) {
            const int row = bm + wm * 64 + i * 16 + lr;
            const int col = bn + wn * 64 + j * 8 + lc;
            const int colN = col & (NF - 1);
            float v0 = acc[i][j][0], v1 = acc[i][j][1];
            float v2 = acc[i][j][2], v3 = acc[i][j][3];
            if (biasp) {
                const float b0 = biasp[colN], b1 = biasp[colN + 1];
                v0 = sigf(v0 + b0); v1 = sigf(v1 + b1);
                v2 = sigf(v2 + b0); v3 = sigf(v3 + b1);
            }
            *(float2*)&outp[(size_t)row * NF + colN]       = make_float2(v0, v1);
            *(float2*)&outp[(size_t)(row + 8) * NF + colN] = make_float2(v2, v3);
        }
    }
}

// ---------------------------------------------------------------------------
// fp32 -> fp16 conversions
// ---------------------------------------------------------------------------
__global__ void conv_kernel(const float* __restrict__ in,
                            __half* __restrict__ out, int total4)
{
    int i = blockIdx.x * blockDim.x + threadIdx.x;
    if (i >= total4) return;
    float4 v = ((const float4*)in)[i];
    ((__half2*)out)[2*i]   = __floats2half2_rn(v.x, v.y);
    ((__half2*)out)[2*i+1] = __floats2half2_rn(v.z, v.w);
}

__global__ void conv2_kernel(const float* __restrict__ inA, __half* __restrict__ outA,
                             const float* __restrict__ inB, __half* __restrict__ outB,
                             int total4)
{
    int i = blockIdx.x * blockDim.x + threadIdx.x;
    if (i >= total4) return;
    float4 v = ((const float4*)inA)[i];
    ((__half2*)outA)[2*i]   = __floats2half2_rn(v.x, v.y);
    ((__half2*)outA)[2*i+1] = __floats2half2_rn(v.z, v.w);
    float4 w = ((const float4*)inB)[i];
    ((__half2*)outB)[2*i]   = __floats2half2_rn(w.x, w.y);
    ((__half2*)outB)[2*i+1] = __floats2half2_rn(w.z, w.w);
}

// ---------------------------------------------------------------------------
// Chunked scan, 3 passes (unchanged from R9)
// ---------------------------------------------------------------------------
__global__ void scan_p1(void)
{
    const int c  = blockIdx.x * blockDim.x + threadIdx.x;
    const int ch = blockIdx.y;
    if (c >= NCHAN) return;
    const int b = c >> 10;
    const int m = c & (NF - 1);

    size_t idx = (size_t)b * TT * NF + (size_t)ch * CHT * NF + m;
    float a = 1.0f, bs = 0.0f;
#pragma unroll 8
    for (int t = 0; t < CHT; t++) {
        const float r  = g_r[idx];
        const float xi = g_wi[idx] * g_wig[idx];
        bs = fmaf(bs, r, xi);
        a *= r;
        idx += NF;
    }
    g_sa[ch * NCHAN + c] = a;
    g_sb[ch * NCHAN + c] = bs;
}

__global__ void scan_p2(const float* __restrict__ mem0,
                        float* __restrict__ mem_out)
{
    const int c = blockIdx.x * blockDim.x + threadIdx.x;
    if (c >= NCHAN) return;
    float h = mem0[c];
#pragma unroll
    for (int ch = 0; ch < NCH; ch++) {
        g_hs[ch * NCHAN + c] = h;
        h = fmaf(h, g_sa[ch * NCHAN + c], g_sb[ch * NCHAN + c]);
    }
    mem_out[c] = h;
}

__global__ void scan_p3(void)
{
    const int c  = blockIdx.x * blockDim.x + threadIdx.x;
    const int ch = blockIdx.y;
    if (c >= NCHAN) return;
    const int b = c >> 10;
    const int m = c & (NF - 1);

    float h = g_hs[ch * NCHAN + c];
    size_t idx = (size_t)b * TT * NF + (size_t)ch * CHT * NF + m;
#pragma unroll 8
    for (int t = 0; t < CHT; t++) {
        const float r  = g_r[idx];
        const float xi = g_wi[idx] * g_wig[idx];
        h = fmaf(h, r, xi);
        const float z = (h / (1.0f + fabsf(h))) * g_og[idx];
        g_zh[idx] = __float2half_rn(z);
        idx += NF;
    }
}

// ---------------------------------------------------------------------------
// Host side
// ---------------------------------------------------------------------------
typedef CUresult (*PFN_encodeTiled)(
    CUtensorMap*, CUtensorMapDataType, cuuint32_t, void*,
    const cuuint64_t*, const cuuint64_t*, const cuuint32_t*, const cuuint32_t*,
    CUtensorMapInterleave, CUtensorMapSwizzle, CUtensorMapL2promotion,
    CUtensorMapFloatOOBfill);

static void make_map2d(PFN_encodeTiled enc, CUtensorMap* tm, void* ptr, uint64_t rows)
{
    cuuint64_t dims[2]    = {(cuuint64_t)KK, (cuuint64_t)rows};
    cuuint64_t strides[1] = {(cuuint64_t)KK * 2};
    cuuint32_t box[2]     = {BK, BM};
    cuuint32_t estr[2]    = {1, 1};
    enc(tm, CU_TENSOR_MAP_DATA_TYPE_FLOAT16, 2, ptr, dims, strides, box, estr,
        CU_TENSOR_MAP_INTERLEAVE_NONE, CU_TENSOR_MAP_SWIZZLE_128B,
        CU_TENSOR_MAP_L2_PROMOTION_L2_128B, CU_TENSOR_MAP_FLOAT_OOB_FILL_NONE);
}

extern "C" void kernel_launch(void* const* d_in, const int* in_sizes, int n_in,
                              void* d_out, int out_size)
{
    const float* x     = (const float*)d_in[0];
    const float* mem0  = (const float*)d_in[1];
    const float* wr_w  = (const float*)d_in[2];
    const float* wr_b  = (const float*)d_in[3];
    const float* wi_w  = (const float*)d_in[4];
    const float* wig_w = (const float*)d_in[5];
    const float* wig_b = (const float*)d_in[6];
    const float* wog_w = (const float*)d_in[7];
    const float* wog_b = (const float*)d_in[8];
    const float* wo_w  = (const float*)d_in[9];

    float* y       = (float*)d_out;
    float* mem_out = y + (size_t)BT * NF;

    float *p_wi, *p_wig, *p_r, *p_og;
    __half *p_xh, *p_zh, *p_w4, *p_woh;
    cudaGetSymbolAddress((void**)&p_wi,  g_wi);
    cudaGetSymbolAddress((void**)&p_wig, g_wig);
    cudaGetSymbolAddress((void**)&p_r,   g_r);
    cudaGetSymbolAddress((void**)&p_og,  g_og);
    cudaGetSymbolAddress((void**)&p_xh,  g_xh);
    cudaGetSymbolAddress((void**)&p_zh,  g_zh);
    cudaGetSymbolAddress((void**)&p_w4,  g_w4);
    cudaGetSymbolAddress((void**)&p_woh, g_woh);

    const size_t ws = (size_t)NF * NF;

    PFN_encodeTiled enc = nullptr;
    {
        cudaDriverEntryPointQueryResult st;
        cudaGetDriverEntryPoint("cuTensorMapEncodeTiled", (void**)&enc,
                                cudaEnableDefault, &st);
    }
    CUtensorMap tmA1, tmB1, tmA2, tmB2;
    make_map2d(enc, &tmA1, p_xh, BT);
    make_map2d(enc, &tmB1, p_w4, 4 * NF);
    make_map2d(enc, &tmA2, p_zh, BT);
    make_map2d(enc, &tmB2, p_woh, NF);

    cudaFuncSetAttribute(hgemm_tma, cudaFuncAttributeMaxDynamicSharedMemorySize, SMEM_BYTES);

    // 1. conversions (4 launches)
    {
        int wt4 = (NF * NF) / 4;
        int wb = (wt4 + 255) / 256;
        conv2_kernel<<<wb, 256>>>(wr_w,  p_w4 + 0 * ws, wi_w,  p_w4 + 1 * ws, wt4);
        conv2_kernel<<<wb, 256>>>(wig_w, p_w4 + 2 * ws, wog_w, p_w4 + 3 * ws, wt4);
        conv_kernel<<<wb, 256>>>(wo_w, p_woh, wt4);
        int xt4 = (BT * NF) / 4;
        conv_kernel<<<(xt4 + 255) / 256, 256>>>(x, p_xh, xt4);
    }

    // 2. fused input projections: C[16384, 4096]
    {
        EpiArgs ea;
        ea.out[0] = p_r;   ea.bias[0] = wr_b;
        ea.out[1] = p_wi;  ea.bias[1] = nullptr;
        ea.out[2] = p_wig; ea.bias[2] = wig_b;
        ea.out[3] = p_og;  ea.bias[3] = wog_b;
        dim3 grid(4 * NF / BN, BT / BM);   // (32, 128)
        hgemm_tma<<<grid, 128, SMEM_BYTES>>>(tmA1, tmB1, ea);
    }

    // 3. chunked recurrence scan
    {
        dim3 g1(NCHAN / 256, NCH);
        scan_p1<<<g1, 256>>>();
        scan_p2<<<NCHAN / 256, 256>>>(mem0, mem_out);
        scan_p3<<<g1, 256>>>();
    }

    // 4. output projection: y = z @ wo^T
    {
        EpiArgs ea;
        ea.out[0] = y;       ea.bias[0] = nullptr;
        ea.out[1] = nullptr; ea.bias[1] = nullptr;
        ea.out[2] = nullptr; ea.bias[2] = nullptr;
        ea.out[3] = nullptr; ea.bias[3] = nullptr;
        dim3 grid(NF / BN, BT / BM);       // (8, 128)
        hgemm_tma<<<grid, 128, SMEM_BYTES>>>(tmA2, tmB2, ea);
    }
}

// round 11
// speedup vs baseline: 1.4863x; 1.4863x over previous
#include <cuda_runtime.h>
#include <cuda.h>
#include <cuda_fp16.h>
#include <math.h>
#include <stdint.h>

#define BB 8
#define TT 2048
#define NF 1024
#define BT (BB*TT)            // 16384
#define KK NF                 // GEMM K = 1024
#define NCH 16                // scan chunks
#define CHT (TT/NCH)          // 128
#define NCHAN (BB*NF)         // 8192

// GEMM tiling: 128x128x64 block, 128 threads, 4 warps (2x2) of 64x64, TMA loads
#define BM 128
#define BN 128
#define BK 64                 // halves; 128 bytes -> SW128 row
#define STAGES 3
#define NKIT (KK/BK)          // 16
#define TILEB (BM*BK*2)       // 16384 bytes per A (or B) tile
#define SM_FULL 0             // 3 x 8B mbarriers
#define SM_TILES 1024
#define SMEM_BYTES (SM_TILES + STAGES*2*TILEB)   // 99328

// ---------------- scratch (device globals; no allocs allowed) ----------------
__device__ float g_wi [(size_t)BT*NF];
__device__ float g_wig[(size_t)BT*NF];
__device__ float g_r  [(size_t)BT*NF];
__device__ float g_og [(size_t)BT*NF];
__device__ __half g_xh [(size_t)BT*NF];
__device__ __half g_zh [(size_t)BT*NF];
__device__ __half g_w4 [(size_t)4*NF*NF];      // proj weights fp16: r, i, ig, og
__device__ __half g_woh[(size_t)NF*NF];
__device__ float g_sa [NCH*NCHAN];
__device__ float g_sb [NCH*NCHAN];
__device__ float g_hs [NCH*NCHAN];

__device__ __forceinline__ float sigf(float v) {
    return 1.0f / (1.0f + __expf(-v));
}
__device__ __forceinline__ uint32_t smem_u32(const void* p) {
    return (uint32_t)__cvta_generic_to_shared(p);
}

#define MMA_F16(d, a, b)                                               \
    asm volatile(                                                      \
        "mma.sync.aligned.m16n8k16.row.col.f32.f16.f16.f32 "           \
        "{%0,%1,%2,%3},{%4,%5,%6,%7},{%8,%9},{%0,%1,%2,%3};\n"         \
        : "+f"(d[0]), "+f"(d[1]), "+f"(d[2]), "+f"(d[3])               \
        : "r"(a[0]), "r"(a[1]), "r"(a[2]), "r"(a[3]),                  \
          "r"(b[0]), "r"(b[1]))

#define LDMX4(r0, r1, r2, r3, addr)                                            \
    asm volatile("ldmatrix.sync.aligned.m8n8.x4.shared.b16 {%0,%1,%2,%3},[%4];\n" \
                 : "=r"(r0), "=r"(r1), "=r"(r2), "=r"(r3) : "r"(addr))

#define MBAR_INIT(addr, cnt) \
    asm volatile("mbarrier.init.shared.b64 [%0], %1;" :: "r"(addr), "r"(cnt) : "memory")
#define MBAR_EXPECT_TX(addr, bytes) \
    asm volatile("mbarrier.arrive.expect_tx.shared.b64 _, [%0], %1;" :: "r"(addr), "r"(bytes) : "memory")

__device__ __forceinline__ void mbar_wait(uint32_t addr, uint32_t parity) {
    uint32_t done;
    asm volatile(
        "{\n\t.reg .pred p;\n\t"
        "mbarrier.try_wait.parity.acquire.cta.shared::cta.b64 p, [%1], %2;\n\t"
        "selp.b32 %0, 1, 0, p;\n\t}"
        : "=r"(done) : "r"(addr), "r"(parity) : "memory");
    if (!done) {
        asm volatile(
            "{\n\t.reg .pred P1;\n\t"
            "WL_%=:\n\t"
            "mbarrier.try_wait.parity.acquire.cta.shared::cta.b64 P1, [%0], %1, 0x989680;\n\t"
            "@P1 bra.uni WD_%=;\n\t"
            "bra.uni WL_%=;\n\t"
            "WD_%=:\n\t}"
            :: "r"(addr), "r"(parity) : "memory");
    }
}

__device__ __forceinline__ void tma2d(uint32_t smem_addr, const CUtensorMap* tmap,
                                      int cx, int cy, uint32_t mbar) {
    asm volatile(
        "cp.async.bulk.tensor.2d.shared::cta.global.tile.mbarrier::complete_tx::bytes "
        "[%0], [%1, {%2, %3}], [%4];"
        :: "r"(smem_addr), "l"(tmap), "r"(cx), "r"(cy), "r"(mbar) : "memory");
}

// SW128 swizzle for a [rows x 128B] tile
__device__ __forceinline__ uint32_t sw128(uint32_t off) {
    return off ^ ((off >> 3) & 0x70);
}

struct EpiArgs {
    float* out[4];
    const float* bias[4];
};

// ---------------------------------------------------------------------------
// fp16 HMMA GEMM with TMA loads: C[i,j] = sum_k A[i,k]*B[j,k]
// 128x128x64 block, 128 thr, 4 warps (2m x 2n) of 64x64.
// 3-stage TMA ring, low-overhead sync: one FULL-wait + one __syncthreads per kt;
// refill of stage s issued by tid0 right after the sync (no FREE barrier).
// ---------------------------------------------------------------------------
__global__ void __launch_bounds__(128, 2)
hgemm_tma(const __grid_constant__ CUtensorMap tmA,
          const __grid_constant__ CUtensorMap tmB,
          EpiArgs ea)
{
    extern __shared__ __align__(1024) char smem[];
    const uint32_t sb = smem_u32(smem);
    const int tid  = threadIdx.x;
    const int warp = tid >> 5, lane = tid & 31;
    const int wm = warp >> 1, wn = warp & 1;
    const int bm = blockIdx.y * BM;
    const int bn = blockIdx.x * BN;

    if (tid == 0) {
#pragma unroll
        for (int s = 0; s < STAGES; s++) MBAR_INIT(sb + SM_FULL + 8*s, 1);
        asm volatile("fence.proxy.async.shared::cta;" ::: "memory");
    }
    __syncthreads();

    if (tid == 0) {
        const CUtensorMap* pA = &tmA;
        const CUtensorMap* pB = &tmB;
        asm volatile("prefetch.tensormap [%0];" :: "l"(pA));
        asm volatile("prefetch.tensormap [%0];" :: "l"(pB));
#pragma unroll
        for (int p = 0; p < STAGES; p++) {
            MBAR_EXPECT_TX(sb + SM_FULL + 8*p, 2u * TILEB);
            tma2d(sb + SM_TILES + p*2*TILEB,         pA, p*BK, bm, sb + SM_FULL + 8*p);
            tma2d(sb + SM_TILES + p*2*TILEB + TILEB, pB, p*BK, bn, sb + SM_FULL + 8*p);
        }
    }

    float acc[4][8][4];
#pragma unroll
    for (int i = 0; i < 4; i++)
#pragma unroll
        for (int j = 0; j < 8; j++)
#pragma unroll
            for (int q = 0; q < 4; q++) acc[i][j][q] = 0.0f;

    uint32_t af[2][4][4], bf[2][8][2];

    // swizzled in-tile byte offsets (row*128 + ks*32 + (lane>>4)*16)
    const uint32_t a_row = wm * 64 + (lane & 15);
    const uint32_t b_row = wn * 64 + (lane & 15);
    const uint32_t coff  = (lane >> 4) * 16;

#define LDFRAG(buf, sbase, ks)                                                     \
    do {                                                                           \
        _Pragma("unroll")                                                          \
        for (int i = 0; i < 4; i++) {                                              \
            uint32_t off = (a_row + i * 16) * 128 + (ks) * 32 + coff;              \
            LDMX4(af[buf][i][0], af[buf][i][1], af[buf][i][2], af[buf][i][3],      \
                  (sbase) + sw128(off));                                           \
        }                                                                          \
        _Pragma("unroll")                                                          \
        for (int g = 0; g < 4; g++) {                                              \
            uint32_t t0, t1, t2, t3;                                               \
            uint32_t off = (b_row + g * 16) * 128 + (ks) * 32 + coff;              \
            LDMX4(t0, t1, t2, t3, (sbase) + TILEB + sw128(off));                   \
            bf[buf][2*g][0]   = t0; bf[buf][2*g][1]   = t2;                        \
            bf[buf][2*g+1][0] = t1; bf[buf][2*g+1][1] = t3;                        \
        }                                                                          \
    } while (0)

#define DO_MMA(buf)                                                \
    do {                                                           \
        _Pragma("unroll")                                          \
        for (int i = 0; i < 4; i++)                                \
            _Pragma("unroll")                                      \
            for (int j = 0; j < 8; j++)                            \
                MMA_F16(acc[i][j], af[buf][i], bf[buf][j]);        \
    } while (0)

    int fullph[STAGES] = {0, 0, 0};

#pragma unroll 1
    for (int kt = 0; kt < NKIT; kt++) {
        const int s = kt % STAGES;
        const uint32_t sbase = sb + SM_TILES + s * 2 * TILEB;

        mbar_wait(sb + SM_FULL + 8*s, fullph[s]);
        fullph[s] ^= 1;

        LDFRAG(0, sbase, 0);
#pragma unroll
        for (int ks = 0; ks < 4; ks++) {
            if (ks < 3) LDFRAG((ks + 1) & 1, sbase, ks + 1);
            DO_MMA(ks & 1);
        }

        // all warps done reading stage s -> safe to refill it for kt+STAGES
        __syncthreads();
        if (tid == 0 && kt + STAGES < NKIT) {
            MBAR_EXPECT_TX(sb + SM_FULL + 8*s, 2u * TILEB);
            tma2d(sbase,         &tmA, (kt + STAGES) * BK, bm, sb + SM_FULL + 8*s);
            tma2d(sbase + TILEB, &tmB, (kt + STAGES) * BK, bn, sb + SM_FULL + 8*s);
        }
    }

    // ---- epilogue ----
    const int seg = bn >> 10;
    float* outp = ea.out[seg];
    const float* biasp = ea.bias[seg];
    const int lr = lane >> 2;
    const int lc = (lane & 3) * 2;

#pragma unroll
    for (int i = 0; i < 4; i++) {
#pragma unroll
        for (int j = 0; j < 8; j++) {
            const int row = bm + wm * 64 + i * 16 + lr;
            const int col = bn + wn * 64 + j * 8 + lc;
            const int colN = col & (NF - 1);
            float v0 = acc[i][j][0], v1 = acc[i][j][1];
            float v2 = acc[i][j][2], v3 = acc[i][j][3];
            if (biasp) {
                const float b0 = biasp[colN], b1 = biasp[colN + 1];
                v0 = sigf(v0 + b0); v1 = sigf(v1 + b1);
                v2 = sigf(v2 + b0); v3 = sigf(v3 + b1);
            }
            *(float2*)&outp[(size_t)row * NF + colN]       = make_float2(v0, v1);
            *(float2*)&outp[(size_t)(row + 8) * NF + colN] = make_float2(v2, v3);
        }
    }
}

// ---------------------------------------------------------------------------
// fp32 -> fp16 conversions
// ---------------------------------------------------------------------------
__global__ void conv_kernel(const float* __restrict__ in,
                            __half* __restrict__ out, int total4)
{
    int i = blockIdx.x * blockDim.x + threadIdx.x;
    if (i >= total4) return;
    float4 v = ((const float4*)in)[i];
    ((__half2*)out)[2*i]   = __floats2half2_rn(v.x, v.y);
    ((__half2*)out)[2*i+1] = __floats2half2_rn(v.z, v.w);
}

__global__ void conv2_kernel(const float* __restrict__ inA, __half* __restrict__ outA,
                             const float* __restrict__ inB, __half* __restrict__ outB,
                             int total4)
{
    int i = blockIdx.x * blockDim.x + threadIdx.x;
    if (i >= total4) return;
    float4 v = ((const float4*)inA)[i];
    ((__half2*)outA)[2*i]   = __floats2half2_rn(v.x, v.y);
    ((__half2*)outA)[2*i+1] = __floats2half2_rn(v.z, v.w);
    float4 w = ((const float4*)inB)[i];
    ((__half2*)outB)[2*i]   = __floats2half2_rn(w.x, w.y);
    ((__half2*)outB)[2*i+1] = __floats2half2_rn(w.z, w.w);
}

// ---------------------------------------------------------------------------
// Chunked scan, 3 passes (unchanged, proven)
// ---------------------------------------------------------------------------
__global__ void scan_p1(void)
{
    const int c  = blockIdx.x * blockDim.x + threadIdx.x;
    const int ch = blockIdx.y;
    if (c >= NCHAN) return;
    const int b = c >> 10;
    const int m = c & (NF - 1);

    size_t idx = (size_t)b * TT * NF + (size_t)ch * CHT * NF + m;
    float a = 1.0f, bs = 0.0f;
#pragma unroll 8
    for (int t = 0; t < CHT; t++) {
        const float r  = g_r[idx];
        const float xi = g_wi[idx] * g_wig[idx];
        bs = fmaf(bs, r, xi);
        a *= r;
        idx += NF;
    }
    g_sa[ch * NCHAN + c] = a;
    g_sb[ch * NCHAN + c] = bs;
}

__global__ void scan_p2(const float* __restrict__ mem0,
                        float* __restrict__ mem_out)
{
    const int c = blockIdx.x * blockDim.x + threadIdx.x;
    if (c >= NCHAN) return;
    float h = mem0[c];
#pragma unroll
    for (int ch = 0; ch < NCH; ch++) {
        g_hs[ch * NCHAN + c] = h;
        h = fmaf(h, g_sa[ch * NCHAN + c], g_sb[ch * NCHAN + c]);
    }
    mem_out[c] = h;
}

__global__ void scan_p3(void)
{
    const int c  = blockIdx.x * blockDim.x + threadIdx.x;
    const int ch = blockIdx.y;
    if (c >= NCHAN) return;
    const int b = c >> 10;
    const int m = c & (NF - 1);

    float h = g_hs[ch * NCHAN + c];
    size_t idx = (size_t)b * TT * NF + (size_t)ch * CHT * NF + m;
#pragma unroll 8
    for (int t = 0; t < CHT; t++) {
        const float r  = g_r[idx];
        const float xi = g_wi[idx] * g_wig[idx];
        h = fmaf(h, r, xi);
        const float z = (h / (1.0f + fabsf(h))) * g_og[idx];
        g_zh[idx] = __float2half_rn(z);
        idx += NF;
    }
}

// ---------------------------------------------------------------------------
// Host side
// ---------------------------------------------------------------------------
typedef CUresult (*PFN_encodeTiled)(
    CUtensorMap*, CUtensorMapDataType, cuuint32_t, void*,
    const cuuint64_t*, const cuuint64_t*, const cuuint32_t*, const cuuint32_t*,
    CUtensorMapInterleave, CUtensorMapSwizzle, CUtensorMapL2promotion,
    CUtensorMapFloatOOBfill);

static void make_map2d(PFN_encodeTiled enc, CUtensorMap* tm, void* ptr, uint64_t rows)
{
    cuuint64_t dims[2]    = {(cuuint64_t)KK, (cuuint64_t)rows};
    cuuint64_t strides[1] = {(cuuint64_t)KK * 2};
    cuuint32_t box[2]     = {BK, BM};
    cuuint32_t estr[2]    = {1, 1};
    enc(tm, CU_TENSOR_MAP_DATA_TYPE_FLOAT16, 2, ptr, dims, strides, box, estr,
        CU_TENSOR_MAP_INTERLEAVE_NONE, CU_TENSOR_MAP_SWIZZLE_128B,
        CU_TENSOR_MAP_L2_PROMOTION_L2_128B, CU_TENSOR_MAP_FLOAT_OOB_FILL_NONE);
}

extern "C" void kernel_launch(void* const* d_in, const int* in_sizes, int n_in,
                              void* d_out, int out_size)
{
    const float* x     = (const float*)d_in[0];
    const float* mem0  = (const float*)d_in[1];
    const float* wr_w  = (const float*)d_in[2];
    const float* wr_b  = (const float*)d_in[3];
    const float* wi_w  = (const float*)d_in[4];
    const float* wig_w = (const float*)d_in[5];
    const float* wig_b = (const float*)d_in[6];
    const float* wog_w = (const float*)d_in[7];
    const float* wog_b = (const float*)d_in[8];
    const float* wo_w  = (const float*)d_in[9];

    float* y       = (float*)d_out;
    float* mem_out = y + (size_t)BT * NF;

    float *p_wi, *p_wig, *p_r, *p_og;
    __half *p_xh, *p_zh, *p_w4, *p_woh;
    cudaGetSymbolAddress((void**)&p_wi,  g_wi);
    cudaGetSymbolAddress((void**)&p_wig, g_wig);
    cudaGetSymbolAddress((void**)&p_r,   g_r);
    cudaGetSymbolAddress((void**)&p_og,  g_og);
    cudaGetSymbolAddress((void**)&p_xh,  g_xh);
    cudaGetSymbolAddress((void**)&p_zh,  g_zh);
    cudaGetSymbolAddress((void**)&p_w4,  g_w4);
    cudaGetSymbolAddress((void**)&p_woh, g_woh);

    const size_t ws = (size_t)NF * NF;

    PFN_encodeTiled enc = nullptr;
    {
        cudaDriverEntryPointQueryResult st;
        cudaGetDriverEntryPoint("cuTensorMapEncodeTiled", (void**)&enc,
                                cudaEnableDefault, &st);
    }
    CUtensorMap tmA1, tmB1, tmA2, tmB2;
    make_map2d(enc, &tmA1, p_xh, BT);
    make_map2d(enc, &tmB1, p_w4, 4 * NF);
    make_map2d(enc, &tmA2, p_zh, BT);
    make_map2d(enc, &tmB2, p_woh, NF);

    cudaFuncSetAttribute(hgemm_tma, cudaFuncAttributeMaxDynamicSharedMemorySize, SMEM_BYTES);

    // 1. conversions (4 launches)
    {
        int wt4 = (NF * NF) / 4;
        int wb = (wt4 + 255) / 256;
        conv2_kernel<<<wb, 256>>>(wr_w,  p_w4 + 0 * ws, wi_w,  p_w4 + 1 * ws, wt4);
        conv2_kernel<<<wb, 256>>>(wig_w, p_w4 + 2 * ws, wog_w, p_w4 + 3 * ws, wt4);
        conv_kernel<<<wb, 256>>>(wo_w, p_woh, wt4);
        int xt4 = (BT * NF) / 4;
        conv_kernel<<<(xt4 + 255) / 256, 256>>>(x, p_xh, xt4);
    }

    // 2. fused input projections: C[16384, 4096]
    {
        EpiArgs ea;
        ea.out[0] = p_r;   ea.bias[0] = wr_b;
        ea.out[1] = p_wi;  ea.bias[1] = nullptr;
        ea.out[2] = p_wig; ea.bias[2] = wig_b;
        ea.out[3] = p_og;  ea.bias[3] = wog_b;
        dim3 grid(4 * NF / BN, BT / BM);   // (32, 128)
        hgemm_tma<<<grid, 128, SMEM_BYTES>>>(tmA1, tmB1, ea);
    }

    // 3. chunked recurrence scan
    {
        dim3 g1(NCHAN / 256, NCH);
        scan_p1<<<g1, 256>>>();
        scan_p2<<<NCHAN / 256, 256>>>(mem0, mem_out);
        scan_p3<<<g1, 256>>>();
    }

    // 4. output projection: y = z @ wo^T
    {
        EpiArgs ea;
        ea.out[0] = y;       ea.bias[0] = nullptr;
        ea.out[1] = nullptr; ea.bias[1] = nullptr;
        ea.out[2] = nullptr; ea.bias[2] = nullptr;
        ea.out[3] = nullptr; ea.bias[3] = nullptr;
        dim3 grid(NF / BN, BT / BM);       // (8, 128)
        hgemm_tma<<<grid, 128, SMEM_BYTES>>>(tmA2, tmB2, ea);
    }
}